// round 2
// baseline (speedup 1.0000x reference)
#include <cuda_runtime.h>
#include <cuda_bf16.h>
#include <cstdint>

#define NN 100000
#define EE 1600000
#define DD 64
#define K1 10
#define K2 3
#define NB_SCAN ((NN + 1023) / 1024)

// ---------------- device scratch (allocation-free rule: __device__ globals) ----
__device__ int   g_row[EE];
__device__ int   g_col[EE];
__device__ int   g_deg[NN];
__device__ int   g_cursor[NN];
__device__ float g_dinv[NN];
__device__ int   g_off[NN + 1];
__device__ int   g_part[128];
__device__ int   g_part2[128];
__device__ int   g_csc_src[EE];
__device__ float g_csc_w[EE];
__device__ __align__(16) float g_H1[(size_t)(K1 + 1) * NN * DD];   // 11 slices
__device__ __align__(16) float g_H2[(size_t)(K2 + 1) * NN * DD];   // 4 slices
__device__ __align__(16) float g_Hf[(size_t)NN * DD];              // layer2 output

// ---------------- build kernels ------------------------------------------------
__global__ void k_zero() {
    int i = blockIdx.x * blockDim.x + threadIdx.x;
    if (i < NN) { g_deg[i] = 0; g_cursor[i] = 0; }
}

// edge_index is int32 (JAX x64 disabled): [2, E] row-major
__global__ void k_edges(const int* __restrict__ ei) {
    int e = blockIdx.x * blockDim.x + threadIdx.x;
    if (e >= EE) return;
    int r = ei[e];
    int c = ei[EE + e];
    g_row[e] = r;
    g_col[e] = c;
    atomicAdd(&g_deg[c], 1);
}

__global__ void k_dinv() {
    int i = blockIdx.x * blockDim.x + threadIdx.x;
    if (i >= NN) return;
    float d = (float)g_deg[i];
    g_dinv[i] = (d > 0.0f) ? rsqrtf(d) : 0.0f;
}

// 3-phase exclusive scan of g_deg -> g_off
__global__ void k_scan1() {
    __shared__ int sd[1024];
    int b = blockIdx.x, t = threadIdx.x;
    int i = b * 1024 + t;
    int v = (i < NN) ? g_deg[i] : 0;
    sd[t] = v;
    __syncthreads();
    for (int off = 1; off < 1024; off <<= 1) {
        int x = sd[t];
        if (t >= off) x += sd[t - off];
        __syncthreads();
        sd[t] = x;
        __syncthreads();
    }
    if (i < NN) g_off[i + 1] = sd[t];
    if (t == 1023) g_part[b] = sd[1023];
}

__global__ void k_scan2() {
    __shared__ int sd[128];
    int t = threadIdx.x;
    sd[t] = (t < NB_SCAN) ? g_part[t] : 0;
    __syncthreads();
    for (int off = 1; off < 128; off <<= 1) {
        int x = sd[t];
        if (t >= off) x += sd[t - off];
        __syncthreads();
        sd[t] = x;
        __syncthreads();
    }
    g_part2[t] = (t > 0) ? sd[t - 1] : 0;
}

__global__ void k_scan3() {
    int b = blockIdx.x, t = threadIdx.x;
    int i = b * 1024 + t;
    if (i < NN) g_off[i + 1] += g_part2[b];
    if (b == 0 && t == 0) g_off[0] = 0;
}

__global__ void k_csc_fill() {
    int e = blockIdx.x * blockDim.x + threadIdx.x;
    if (e >= EE) return;
    int r = g_row[e];
    int c = g_col[e];
    int p = g_off[c] + atomicAdd(&g_cursor[c], 1);
    g_csc_src[p] = r;
    g_csc_w[p] = g_dinv[r] * g_dinv[c];
}

__global__ void k_copy_x(const float* __restrict__ x) {
    int i = blockIdx.x * blockDim.x + threadIdx.x;
    if (i < NN * DD) g_H1[i] = x[i];
}

// ---------------- SpMM: one warp per destination node, no atomics --------------
__global__ void __launch_bounds__(256) k_spmm(int which, int si, int so) {
    int warp = (blockIdx.x * blockDim.x + threadIdx.x) >> 5;
    int lane = threadIdx.x & 31;
    if (warp >= NN) return;
    float* base = (which == 0) ? g_H1 : g_H2;
    const float* __restrict__ hin = base + (size_t)si * NN * DD;
    float* __restrict__ hout = base + (size_t)so * NN * DD;
    int s = g_off[warp], e = g_off[warp + 1];
    float a0 = 0.f, a1 = 0.f;
#pragma unroll 4
    for (int p = s; p < e; p++) {
        int src = __ldg(&g_csc_src[p]);
        float wt = __ldg(&g_csc_w[p]);
        const float* hp = hin + (size_t)src * DD;
        a0 += wt * __ldg(hp + lane);
        a1 += wt * __ldg(hp + lane + 32);
    }
    hout[(size_t)warp * DD + lane]      = a0;
    hout[(size_t)warp * DD + lane + 32] = a1;
}

// ---------------- fused multi-slice GEMM ---------------------------------------
// C[r][c] = (tanh?)( sum_s sum_i A[s][r][i] * W[s*64+i][c] + bias[c] )
// BM=256 rows, 256 threads, 8x8 micro-tile (strided rows by 32, cols by 8).
// Shared: As4[256][17] float4 (pad 17 -> conflict-free), WsT[64][68] floats.
__global__ void __launch_bounds__(256, 2) k_gemm(
    int whichA, int nsl,
    const float* __restrict__ W, const float* __restrict__ bias,
    int whichOut, float* __restrict__ dext, int dotanh)
{
    extern __shared__ float sm[];
    float4* As4 = (float4*)sm;                      // 256*17 float4 = 69632 B
    float*  WsT = sm + 256 * 17 * 4;                // 64*68 floats  = 17408 B
    const float4* WsT4 = (const float4*)WsT;

    const float* A = (whichA == 0) ? g_H1 : (whichA == 1) ? g_H2 : g_Hf;
    float* Cout = (whichOut == 0) ? g_H2 : (whichOut == 1) ? g_Hf : dext;

    int t = threadIdx.x;
    int w = t >> 5, l = t & 31;
    int rowg = l & 3, colg = l >> 2;
    int base_r = w * 4 + rowg;          // 0..31 ; thread rows: base_r + 32*i
    int rowBase = blockIdx.x * 256;

    float acc[8][8];
#pragma unroll
    for (int i = 0; i < 8; i++)
#pragma unroll
        for (int j = 0; j < 8; j++) acc[i][j] = 0.f;

    for (int s = 0; s < nsl; s++) {
        const float4* Ag = (const float4*)(A + (size_t)s * NN * DD);
#pragma unroll
        for (int it = 0; it < 16; it++) {
            int idx = t + 256 * it;          // 0..4095
            int row = idx >> 4, k4 = idx & 15;
            int gr = rowBase + row;
            float4 v = make_float4(0.f, 0.f, 0.f, 0.f);
            if (gr < NN) v = Ag[gr * 16 + k4];
            As4[row * 17 + k4] = v;
        }
        const float4* Wg = (const float4*)(W + (size_t)s * 4096);
#pragma unroll
        for (int it = 0; it < 4; it++) {
            int idx = t + 256 * it;          // 0..1023
            int k = idx >> 4, c4 = idx & 15;
            float4 v = Wg[k * 16 + c4];
            WsT[(4 * c4 + 0) * 68 + k] = v.x;
            WsT[(4 * c4 + 1) * 68 + k] = v.y;
            WsT[(4 * c4 + 2) * 68 + k] = v.z;
            WsT[(4 * c4 + 3) * 68 + k] = v.w;
        }
        __syncthreads();
#pragma unroll
        for (int k4 = 0; k4 < 16; k4++) {
            float4 b4[8];
#pragma unroll
            for (int j = 0; j < 8; j++) b4[j] = WsT4[(colg + 8 * j) * 17 + k4];
#pragma unroll
            for (int i = 0; i < 8; i++) {
                float4 a = As4[(base_r + 32 * i) * 17 + k4];
#pragma unroll
                for (int j = 0; j < 8; j++) {
                    acc[i][j] += a.x * b4[j].x;
                    acc[i][j] += a.y * b4[j].y;
                    acc[i][j] += a.z * b4[j].z;
                    acc[i][j] += a.w * b4[j].w;
                }
            }
        }
        __syncthreads();
    }

#pragma unroll
    for (int i = 0; i < 8; i++) {
        int gr = rowBase + base_r + 32 * i;
        if (gr >= NN) continue;
#pragma unroll
        for (int j = 0; j < 8; j++) {
            int c = colg + 8 * j;
            float v = acc[i][j] + bias[c];
            if (dotanh) v = tanhf(v);
            Cout[(size_t)gr * DD + c] = v;
        }
    }
}

// ---------------- launch -------------------------------------------------------
extern "C" void kernel_launch(void* const* d_in, const int* in_sizes, int n_in,
                              void* d_out, int out_size) {
    const float* x  = (const float*)d_in[0];
    const int*   ei = (const int*)d_in[1];     // int32 edge_index [2, E]
    const float* w1 = (const float*)d_in[2];
    const float* b1 = (const float*)d_in[3];
    const float* w2 = (const float*)d_in[4];
    const float* b2 = (const float*)d_in[5];
    const float* wc = (const float*)d_in[6];
    const float* bc = (const float*)d_in[7];
    float* out = (float*)d_out;

    const int SMEM = 256 * 17 * 16 + 64 * 68 * 4;   // 87040
    static int cfg_done = 0;
    if (!cfg_done) {
        cudaFuncSetAttribute(k_gemm, cudaFuncAttributeMaxDynamicSharedMemorySize, SMEM);
        cfg_done = 1;
    }

    // ---- build CSC ----
    k_zero<<<(NN + 255) / 256, 256>>>();
    k_edges<<<(EE + 255) / 256, 256>>>(ei);
    k_dinv<<<(NN + 255) / 256, 256>>>();
    k_scan1<<<NB_SCAN, 1024>>>();
    k_scan2<<<1, 128>>>();
    k_scan3<<<NB_SCAN, 1024>>>();
    k_csc_fill<<<(EE + 255) / 256, 256>>>();

    // ---- layer 1: hops into g_H1 slices ----
    k_copy_x<<<(NN * DD + 255) / 256, 256>>>(x);
    int spmm_blocks = (NN * 32 + 255) / 256;
    for (int k = 1; k <= K1; k++)
        k_spmm<<<spmm_blocks, 256>>>(0, k - 1, k);

    int gemm_blocks = (NN + 255) / 256;
    // out1 = tanh(sum_k H1_k W1_k + b1) -> g_H2 slice 0
    k_gemm<<<gemm_blocks, 256, SMEM>>>(0, K1 + 1, w1, b1, 0, nullptr, 1);

    // ---- layer 2 ----
    for (int k = 1; k <= K2; k++)
        k_spmm<<<spmm_blocks, 256>>>(1, k - 1, k);
    // out2 = tanh(sum_k H2_k W2_k + b2) -> g_Hf
    k_gemm<<<gemm_blocks, 256, SMEM>>>(1, K2 + 1, w2, b2, 1, nullptr, 1);

    // ---- final linear -> d_out ----
    k_gemm<<<gemm_blocks, 256, SMEM>>>(2, 1, wc, bc, 2, out, 0);
}

// round 7
// speedup vs baseline: 1.0019x; 1.0019x over previous
#include <cuda_runtime.h>
#include <cuda_fp16.h>
#include <cstdint>

#define NN 100000
#define EE 1600000
#define DD 64
#define K1 10
#define K2 3
#define NB_SCAN ((NN + 1023) / 1024)

// ---------------- device scratch (allocation-free rule: __device__ globals) ----
__device__ int   g_row[EE];
__device__ int   g_col[EE];
__device__ int   g_deg[NN];
__device__ int   g_cursor[NN];
__device__ float g_dinv[NN];
__device__ int   g_off[NN + 1];
__device__ int   g_part[128];
__device__ int   g_part2[128];
__device__ __align__(16) int2  g_csc[EE];                    // (src, weight-bits)
__device__ __align__(16) float g_H1[(size_t)(K1 + 1) * NN * DD];   // 11 fp32 slices
__device__ __align__(16) float g_H2[(size_t)(K2 + 1) * NN * DD];   // 4 fp32 slices
__device__ __align__(16) float g_Hf[(size_t)NN * DD];              // layer2 output
__device__ __align__(16) __half2 g_F16a[(size_t)NN * 32];          // fp16 ping
__device__ __align__(16) __half2 g_F16b[(size_t)NN * 32];          // fp16 pong

// ---------------- build kernels ------------------------------------------------
__global__ void k_zero() {
    int i = blockIdx.x * blockDim.x + threadIdx.x;
    if (i < NN) { g_deg[i] = 0; g_cursor[i] = 0; }
}

// edge_index is int32 (JAX x64 disabled): [2, E] row-major
__global__ void k_edges(const int* __restrict__ ei) {
    int e = blockIdx.x * blockDim.x + threadIdx.x;
    if (e >= EE) return;
    int r = ei[e];
    int c = ei[EE + e];
    g_row[e] = r;
    g_col[e] = c;
    atomicAdd(&g_deg[c], 1);
}

__global__ void k_dinv() {
    int i = blockIdx.x * blockDim.x + threadIdx.x;
    if (i >= NN) return;
    float d = (float)g_deg[i];
    g_dinv[i] = (d > 0.0f) ? rsqrtf(d) : 0.0f;
}

// 3-phase exclusive scan of g_deg -> g_off
__global__ void k_scan1() {
    __shared__ int sd[1024];
    int b = blockIdx.x, t = threadIdx.x;
    int i = b * 1024 + t;
    int v = (i < NN) ? g_deg[i] : 0;
    sd[t] = v;
    __syncthreads();
    for (int off = 1; off < 1024; off <<= 1) {
        int x = sd[t];
        if (t >= off) x += sd[t - off];
        __syncthreads();
        sd[t] = x;
        __syncthreads();
    }
    if (i < NN) g_off[i + 1] = sd[t];
    if (t == 1023) g_part[b] = sd[1023];
}

__global__ void k_scan2() {
    __shared__ int sd[128];
    int t = threadIdx.x;
    sd[t] = (t < NB_SCAN) ? g_part[t] : 0;
    __syncthreads();
    for (int off = 1; off < 128; off <<= 1) {
        int x = sd[t];
        if (t >= off) x += sd[t - off];
        __syncthreads();
        sd[t] = x;
        __syncthreads();
    }
    g_part2[t] = (t > 0) ? sd[t - 1] : 0;
}

__global__ void k_scan3() {
    int b = blockIdx.x, t = threadIdx.x;
    int i = b * 1024 + t;
    if (i < NN) g_off[i + 1] += g_part2[b];
    if (b == 0 && t == 0) g_off[0] = 0;
}

__global__ void k_csc_fill() {
    int e = blockIdx.x * blockDim.x + threadIdx.x;
    if (e >= EE) return;
    int r = g_row[e];
    int c = g_col[e];
    int p = g_off[c] + atomicAdd(&g_cursor[c], 1);
    g_csc[p] = make_int2(r, __float_as_int(g_dinv[r] * g_dinv[c]));
}

// copy x into fp32 slice 0 of H1 and fp16 ping buffer
__global__ void k_copy_x(const float* __restrict__ x) {
    int i = blockIdx.x * blockDim.x + threadIdx.x;
    if (i >= NN * 32) return;
    float2 v = ((const float2*)x)[i];
    ((float2*)g_H1)[i] = v;
    g_F16a[i] = __floats2half2_rn(v.x, v.y);
}

// fp32 [N,64] -> fp16 ping buffer
__global__ void k_f32tof16(int whichSrc) {
    int i = blockIdx.x * blockDim.x + threadIdx.x;
    if (i >= NN * 32) return;
    const float2* src = (const float2*)((whichSrc == 0) ? g_H2 : g_H1);
    float2 v = src[i];
    g_F16a[i] = __floats2half2_rn(v.x, v.y);
}

// ---------------- SpMM: one warp per destination node, no atomics --------------
// reads fp16 features (one 128B row per edge), accumulates fp32,
// writes fp32 slice (for GEMM) + fp16 buffer (for next hop)
__global__ void __launch_bounds__(256) k_spmm(int srcPing, int whichSlice, int so) {
    int warp = (blockIdx.x * blockDim.x + threadIdx.x) >> 5;
    int lane = threadIdx.x & 31;
    if (warp >= NN) return;
    const __half2* __restrict__ hin = srcPing ? g_F16b : g_F16a;
    __half2* __restrict__ hf = srcPing ? g_F16a : g_F16b;
    float* __restrict__ slice =
        ((whichSlice == 0) ? g_H1 : g_H2) + (size_t)so * NN * DD;
    int s = g_off[warp], e = g_off[warp + 1];
    float a0 = 0.f, a1 = 0.f;
#pragma unroll 4
    for (int p = s; p < e; p++) {
        int2 sw = __ldg(&g_csc[p]);
        float wt = __int_as_float(sw.y);
        float2 v = __half22float2(__ldg(&hin[(size_t)sw.x * 32 + lane]));
        a0 += wt * v.x;
        a1 += wt * v.y;
    }
    ((float2*)slice)[(size_t)warp * 32 + lane] = make_float2(a0, a1);
    hf[(size_t)warp * 32 + lane] = __floats2half2_rn(a0, a1);
}

// ---------------- fused multi-slice GEMM (fp32 SIMT) ---------------------------
// C[r][c] = (tanh?)( sum_s sum_i A[s][r][i] * W[s*64+i][c] + bias[c] )
__global__ void __launch_bounds__(256, 2) k_gemm(
    int whichA, int nsl,
    const float* __restrict__ W, const float* __restrict__ bias,
    int whichOut, float* __restrict__ dext, int dotanh)
{
    extern __shared__ float sm[];
    float4* As4 = (float4*)sm;                      // 256*17 float4 = 69632 B
    float*  WsT = sm + 256 * 17 * 4;                // 64*68 floats  = 17408 B
    const float4* WsT4 = (const float4*)WsT;

    const float* A = (whichA == 0) ? g_H1 : (whichA == 1) ? g_H2 : g_Hf;
    float* Cout = (whichOut == 0) ? g_H2 : (whichOut == 1) ? g_Hf : dext;

    int t = threadIdx.x;
    int w = t >> 5, l = t & 31;
    int rowg = l & 3, colg = l >> 2;
    int base_r = w * 4 + rowg;
    int rowBase = blockIdx.x * 256;

    float acc[8][8];
#pragma unroll
    for (int i = 0; i < 8; i++)
#pragma unroll
        for (int j = 0; j < 8; j++) acc[i][j] = 0.f;

    for (int s = 0; s < nsl; s++) {
        const float4* Ag = (const float4*)(A + (size_t)s * NN * DD);
#pragma unroll
        for (int it = 0; it < 16; it++) {
            int idx = t + 256 * it;
            int row = idx >> 4, k4 = idx & 15;
            int gr = rowBase + row;
            float4 v = make_float4(0.f, 0.f, 0.f, 0.f);
            if (gr < NN) v = Ag[gr * 16 + k4];
            As4[row * 17 + k4] = v;
        }
        const float4* Wg = (const float4*)(W + (size_t)s * 4096);
#pragma unroll
        for (int it = 0; it < 4; it++) {
            int idx = t + 256 * it;
            int k = idx >> 4, c4 = idx & 15;
            float4 v = Wg[k * 16 + c4];
            WsT[(4 * c4 + 0) * 68 + k] = v.x;
            WsT[(4 * c4 + 1) * 68 + k] = v.y;
            WsT[(4 * c4 + 2) * 68 + k] = v.z;
            WsT[(4 * c4 + 3) * 68 + k] = v.w;
        }
        __syncthreads();
#pragma unroll
        for (int k4 = 0; k4 < 16; k4++) {
            float4 b4[8];
#pragma unroll
            for (int j = 0; j < 8; j++) b4[j] = WsT4[(colg + 8 * j) * 17 + k4];
#pragma unroll
            for (int i = 0; i < 8; i++) {
                float4 a = As4[(base_r + 32 * i) * 17 + k4];
#pragma unroll
                for (int j = 0; j < 8; j++) {
                    acc[i][j] += a.x * b4[j].x;
                    acc[i][j] += a.y * b4[j].y;
                    acc[i][j] += a.z * b4[j].z;
                    acc[i][j] += a.w * b4[j].w;
                }
            }
        }
        __syncthreads();
    }

#pragma unroll
    for (int i = 0; i < 8; i++) {
        int gr = rowBase + base_r + 32 * i;
        if (gr >= NN) continue;
#pragma unroll
        for (int j = 0; j < 8; j++) {
            int c = colg + 8 * j;
            float v = acc[i][j] + bias[c];
            if (dotanh) v = tanhf(v);
            Cout[(size_t)gr * DD + c] = v;
        }
    }
}

// ---------------- launch -------------------------------------------------------
extern "C" void kernel_launch(void* const* d_in, const int* in_sizes, int n_in,
                              void* d_out, int out_size) {
    const float* x  = (const float*)d_in[0];
    const int*   ei = (const int*)d_in[1];     // int32 edge_index [2, E]
    const float* w1 = (const float*)d_in[2];
    const float* b1 = (const float*)d_in[3];
    const float* w2 = (const float*)d_in[4];
    const float* b2 = (const float*)d_in[5];
    const float* wc = (const float*)d_in[6];
    const float* bc = (const float*)d_in[7];
    float* out = (float*)d_out;

    const int SMEM = 256 * 17 * 16 + 64 * 68 * 4;   // 87040
    static int cfg_done = 0;
    if (!cfg_done) {
        cudaFuncSetAttribute(k_gemm, cudaFuncAttributeMaxDynamicSharedMemorySize, SMEM);
        cfg_done = 1;
    }

    // ---- build CSC ----
    k_zero<<<(NN + 255) / 256, 256>>>();
    k_edges<<<(EE + 255) / 256, 256>>>(ei);
    k_dinv<<<(NN + 255) / 256, 256>>>();
    k_scan1<<<NB_SCAN, 1024>>>();
    k_scan2<<<1, 128>>>();
    k_scan3<<<NB_SCAN, 1024>>>();
    k_csc_fill<<<(EE + 255) / 256, 256>>>();

    // ---- layer 1: hops into g_H1 slices (fp16 propagate, fp32 slices) ----
    k_copy_x<<<(NN * 32 + 255) / 256, 256>>>(x);
    int spmm_blocks = (NN * 32 + 255) / 256;
    for (int k = 1; k <= K1; k++)
        k_spmm<<<spmm_blocks, 256>>>((k - 1) & 1, 0, k);   // ping-pong

    int gemm_blocks = (NN + 255) / 256;
    // out1 = tanh(sum_k H1_k W1_k + b1) -> g_H2 slice 0
    k_gemm<<<gemm_blocks, 256, SMEM>>>(0, K1 + 1, w1, b1, 0, nullptr, 1);

    // ---- layer 2 ----
    k_f32tof16<<<(NN * 32 + 255) / 256, 256>>>(0);         // H2 slice0 -> F16a
    for (int k = 1; k <= K2; k++)
        k_spmm<<<spmm_blocks, 256>>>((k - 1) & 1, 1, k);
    // out2 = tanh(sum_k H2_k W2_k + b2) -> g_Hf
    k_gemm<<<gemm_blocks, 256, SMEM>>>(1, K2 + 1, w2, b2, 1, nullptr, 1);

    // ---- final linear -> d_out ----
    k_gemm<<<gemm_blocks, 256, SMEM>>>(2, 1, wc, bc, 2, out, 0);
}

// round 9
// speedup vs baseline: 1.7754x; 1.7721x over previous
#include <cuda_runtime.h>
#include <cuda_fp16.h>
#include <cstdint>

#define NN 100000
#define EE 1600000
#define DD 64
#define K1 10
#define K2 3
#define NB_SCAN ((NN + 1023) / 1024)

// ---------------- device scratch (allocation-free rule: __device__ globals) ----
__device__ int   g_deg[NN];
__device__ int   g_cursor[NN];
__device__ float g_dinv[NN];
__device__ int   g_off[NN + 1];
__device__ int   g_part[128];
__device__ __align__(16) int2   g_csc[EE];                          // (src, w-bits)
__device__ __align__(16) __half g_S1[(size_t)(K1 + 1) * NN * DD];   // 11 fp16 slices
__device__ __align__(16) __half g_S2[(size_t)(K2 + 1) * NN * DD];   // 4 fp16 slices
__device__ __align__(16) __half g_Sf[(size_t)NN * DD];              // layer2 out fp16
__device__ __align__(16) __half g_W1h[(K1 + 1) * DD * DD];
__device__ __align__(16) __half g_W2h[(K2 + 1) * DD * DD];
__device__ __align__(16) __half g_Wch[DD * DD];

// ---------------- build kernels ------------------------------------------------
__global__ void k_zero() {
    int i = blockIdx.x * blockDim.x + threadIdx.x;
    if (i < NN) { g_deg[i] = 0; g_cursor[i] = 0; }
}

__global__ void k_deg(const int* __restrict__ ei) {
    int e = blockIdx.x * blockDim.x + threadIdx.x;
    if (e < EE) atomicAdd(&g_deg[ei[EE + e]], 1);
}

// block-scan of deg -> g_off[i+1] (local), block sums -> g_part; also dinv
__global__ void k_scan1() {
    __shared__ int sd[1024];
    int b = blockIdx.x, t = threadIdx.x;
    int i = b * 1024 + t;
    int v = (i < NN) ? g_deg[i] : 0;
    if (i < NN) {
        float d = (float)v;
        g_dinv[i] = (d > 0.0f) ? rsqrtf(d) : 0.0f;
    }
    sd[t] = v;
    __syncthreads();
    for (int off = 1; off < 1024; off <<= 1) {
        int x = sd[t];
        if (t >= off) x += sd[t - off];
        __syncthreads();
        sd[t] = x;
        __syncthreads();
    }
    if (i < NN) g_off[i + 1] = sd[t];
    if (t == 1023) g_part[b] = sd[1023];
}

// each block recomputes the 98-partial prefix locally, adds to its g_off range
__global__ void k_scan3() {
    __shared__ int sp[128];
    int b = blockIdx.x, t = threadIdx.x;
    if (t < 128) sp[t] = (t < NB_SCAN) ? g_part[t] : 0;
    __syncthreads();
    for (int off = 1; off < 128; off <<= 1) {
        int x = 0;
        if (t < 128) { x = sp[t]; if (t >= off) x += sp[t - off]; }
        __syncthreads();
        if (t < 128) sp[t] = x;
        __syncthreads();
    }
    int add = (b > 0) ? sp[b - 1] : 0;
    int i = b * 1024 + t;
    if (i < NN) g_off[i + 1] += add;
    if (b == 0 && t == 0) g_off[0] = 0;
}

// fused: CSC fill (edges) + x -> fp16 slice0 copy. grid = NN*32/256 = 12500
__global__ void k_fillcopy(const int* __restrict__ ei, const float* __restrict__ x) {
    int i = blockIdx.x * blockDim.x + threadIdx.x;
    if (i < NN * 32) {
        float2 v = ((const float2*)x)[i];
        ((__half2*)g_S1)[i] = __floats2half2_rn(v.x, v.y);
    }
    if (i < EE) {
        int r = ei[i];
        int c = ei[EE + i];
        int p = g_off[c] + atomicAdd(&g_cursor[c], 1);
        g_csc[p] = make_int2(r, __float_as_int(g_dinv[r] * g_dinv[c]));
    }
}

// weights fp32 -> fp16 (one tiny launch)
__global__ void k_cvtw(const float* __restrict__ w1, const float* __restrict__ w2,
                       const float* __restrict__ wc) {
    int i = blockIdx.x * blockDim.x + threadIdx.x;
    if (i < (K1 + 1) * DD * DD) g_W1h[i] = __float2half_rn(w1[i]);
    if (i < (K2 + 1) * DD * DD) g_W2h[i] = __float2half_rn(w2[i]);
    if (i < DD * DD)            g_Wch[i] = __float2half_rn(wc[i]);
}

// ---------------- SpMM: one warp per destination node, fp16 slices -------------
__global__ void __launch_bounds__(256) k_spmm(int layer, int si, int so) {
    int warp = (blockIdx.x * blockDim.x + threadIdx.x) >> 5;
    int lane = threadIdx.x & 31;
    if (warp >= NN) return;
    const __half* base = layer ? g_S2 : g_S1;
    const __half2* __restrict__ hin = (const __half2*)(base + (size_t)si * NN * DD);
    __half2* __restrict__ hout = (__half2*)((layer ? g_S2 : g_S1) + (size_t)so * NN * DD);
    int s = g_off[warp], e = g_off[warp + 1];
    float a0 = 0.f, a1 = 0.f;
#pragma unroll 4
    for (int p = s; p < e; p++) {
        int2 sw = __ldg(&g_csc[p]);
        float wt = __int_as_float(sw.y);
        float2 v = __half22float2(__ldg(&hin[(size_t)sw.x * 32 + lane]));
        a0 += wt * v.x;
        a1 += wt * v.y;
    }
    hout[(size_t)warp * 32 + lane] = __floats2half2_rn(a0, a1);
}

// ---------------- tensor-core multi-slice GEMM ---------------------------------
// C[r][c] = (tanh?)( sum_s A_s[r][:] . W_s[:][c] + bias[c] ), fp16 in, fp32 acc.
// 256 threads = 8 warps; block tile 256x64; warp tile 32x64.
__global__ void __launch_bounds__(256, 2) k_mma(
    int whichA, int nsl, int whichW,
    const float* __restrict__ bias,
    int whichOut, float* __restrict__ dext, int dotanh)
{
    __shared__ __half As[256 * 72];   // A tile, 72-half padded rows
    __shared__ __half Ws[64 * 72];    // W^T tile: [n][k], 72-half padded rows

    const __half* A = (whichA == 0) ? g_S1 : (whichA == 1) ? g_S2 : g_Sf;
    const __half* W = (whichW == 0) ? g_W1h : (whichW == 1) ? g_W2h : g_Wch;
    __half* OutH = (whichOut == 0) ? g_S2 : g_Sf;

    int t = threadIdx.x, w = t >> 5, l = t & 31;
    int rowBase = blockIdx.x * 256;

    float acc[2][8][4];
#pragma unroll
    for (int rf = 0; rf < 2; rf++)
#pragma unroll
        for (int j = 0; j < 8; j++)
#pragma unroll
            for (int q = 0; q < 4; q++) acc[rf][j][q] = 0.f;

    for (int s = 0; s < nsl; s++) {
        const __half* Ag = A + (size_t)s * NN * DD;
        // A tile: 2048 16B chunks, coalesced
#pragma unroll
        for (int it = 0; it < 8; it++) {
            int idx = it * 256 + t;              // 0..2047
            int row = idx >> 3, c16 = idx & 7;
            int gr = rowBase + row;
            uint4 v = make_uint4(0, 0, 0, 0);
            if (gr < NN) v = *(const uint4*)(Ag + (size_t)gr * DD + c16 * 8);
            *(uint4*)(&As[row * 72 + c16 * 8]) = v;
        }
        // W^T tile
        const __half* Wg = W + s * DD * DD;
#pragma unroll
        for (int it = 0; it < 16; it++) {
            int idx = it * 256 + t;              // 0..4095
            int k = idx >> 6, n = idx & 63;
            Ws[n * 72 + k] = Wg[idx];
        }
        __syncthreads();

#pragma unroll
        for (int ks = 0; ks < 4; ks++) {
            uint32_t a[2][4];
#pragma unroll
            for (int rf = 0; rf < 2; rf++) {
                int row = w * 32 + rf * 16 + (l & 15);
                uint32_t addr = (uint32_t)__cvta_generic_to_shared(
                    &As[row * 72 + ks * 16 + (l >> 4) * 8]);
                asm volatile("ldmatrix.sync.aligned.m8n8.x4.shared.b16 {%0,%1,%2,%3},[%4];"
                             : "=r"(a[rf][0]), "=r"(a[rf][1]), "=r"(a[rf][2]), "=r"(a[rf][3])
                             : "r"(addr));
            }
#pragma unroll
            for (int j = 0; j < 8; j++) {
                int n = j * 8 + (l >> 2);
                int kk = ks * 16 + (l & 3) * 2;
                uint32_t b0 = *(const uint32_t*)(&Ws[n * 72 + kk]);
                uint32_t b1 = *(const uint32_t*)(&Ws[n * 72 + kk + 8]);
#pragma unroll
                for (int rf = 0; rf < 2; rf++) {
                    asm volatile(
                        "mma.sync.aligned.m16n8k16.row.col.f32.f16.f16.f32 "
                        "{%0,%1,%2,%3},{%4,%5,%6,%7},{%8,%9},{%0,%1,%2,%3};"
                        : "+f"(acc[rf][j][0]), "+f"(acc[rf][j][1]),
                          "+f"(acc[rf][j][2]), "+f"(acc[rf][j][3])
                        : "r"(a[rf][0]), "r"(a[rf][1]), "r"(a[rf][2]), "r"(a[rf][3]),
                          "r"(b0), "r"(b1));
                }
            }
        }
        __syncthreads();
    }

    // epilogue: acc[rf][j]: (r0, c),(r0, c+1) and (r0+8, c),(r0+8, c+1)
#pragma unroll
    for (int rf = 0; rf < 2; rf++) {
#pragma unroll
        for (int j = 0; j < 8; j++) {
            int r0 = rowBase + w * 32 + rf * 16 + (l >> 2);
            int c = j * 8 + (l & 3) * 2;
            float v0 = acc[rf][j][0] + bias[c];
            float v1 = acc[rf][j][1] + bias[c + 1];
            float v2 = acc[rf][j][2] + bias[c];
            float v3 = acc[rf][j][3] + bias[c + 1];
            if (dotanh) {
                v0 = tanhf(v0); v1 = tanhf(v1);
                v2 = tanhf(v2); v3 = tanhf(v3);
            }
            if (whichOut == 2) {
                if (r0 < NN)     *(float2*)&dext[(size_t)r0 * DD + c]       = make_float2(v0, v1);
                if (r0 + 8 < NN) *(float2*)&dext[(size_t)(r0 + 8) * DD + c] = make_float2(v2, v3);
            } else {
                if (r0 < NN)     *(__half2*)&OutH[(size_t)r0 * DD + c]       = __floats2half2_rn(v0, v1);
                if (r0 + 8 < NN) *(__half2*)&OutH[(size_t)(r0 + 8) * DD + c] = __floats2half2_rn(v2, v3);
            }
        }
    }
}

// ---------------- launch -------------------------------------------------------
extern "C" void kernel_launch(void* const* d_in, const int* in_sizes, int n_in,
                              void* d_out, int out_size) {
    const float* x  = (const float*)d_in[0];
    const int*   ei = (const int*)d_in[1];     // int32 edge_index [2, E]
    const float* w1 = (const float*)d_in[2];
    const float* b1 = (const float*)d_in[3];
    const float* w2 = (const float*)d_in[4];
    const float* b2 = (const float*)d_in[5];
    const float* wc = (const float*)d_in[6];
    const float* bc = (const float*)d_in[7];
    float* out = (float*)d_out;

    // ---- build (launch indices 0..4; index 5 = first SpMM for ncu) ----
    k_zero<<<(NN + 255) / 256, 256>>>();
    k_deg<<<(EE + 255) / 256, 256>>>(ei);
    k_scan1<<<NB_SCAN, 1024>>>();
    k_scan3<<<NB_SCAN, 1024>>>();
    k_fillcopy<<<(NN * 32 + 255) / 256, 256>>>(ei, x);

    int spmm_blocks = (NN * 32 + 255) / 256;
    for (int k = 1; k <= K1; k++)
        k_spmm<<<spmm_blocks, 256>>>(0, k - 1, k);

    k_cvtw<<<((K1 + 1) * DD * DD + 255) / 256, 256>>>(w1, w2, wc);

    int gemm_blocks = (NN + 255) / 256;
    // layer1: tanh(sum H1_k W1_k + b1) -> g_S2 slice 0 (fp16)
    k_mma<<<gemm_blocks, 256>>>(0, K1 + 1, 0, b1, 0, nullptr, 1);

    for (int k = 1; k <= K2; k++)
        k_spmm<<<spmm_blocks, 256>>>(1, k - 1, k);
    // layer2: tanh(sum H2_k W2_k + b2) -> g_Sf (fp16)
    k_mma<<<gemm_blocks, 256>>>(1, K2 + 1, 1, b2, 1, nullptr, 1);

    // final linear -> d_out (fp32)
    k_mma<<<gemm_blocks, 256>>>(2, 1, 2, bc, 2, out, 0);
}

// round 11
// speedup vs baseline: 2.0362x; 1.1469x over previous
#include <cuda_runtime.h>
#include <cuda_fp16.h>
#include <cstdint>

#define NN 100000
#define EE 1600000
#define DD 64
#define K1 10
#define K2 3
#define NB_SCAN ((NN + 1023) / 1024)

// ---------------- device scratch (allocation-free rule: __device__ globals) ----
__device__ int   g_deg[NN];
__device__ int   g_cursor[NN];
__device__ float g_dinv[NN];
__device__ int   g_off[NN + 1];
__device__ int   g_part[128];
__device__ __align__(16) int2   g_csc[EE];                          // (src, w-bits)
__device__ __align__(16) __half g_S1[(size_t)(K1 + 1) * NN * DD];   // 11 fp16 slices
__device__ __align__(16) __half g_S2[(size_t)(K2 + 1) * NN * DD];   // 4 fp16 slices
__device__ __align__(16) __half g_Sf[(size_t)NN * DD];              // layer2 out fp16
__device__ __align__(16) __half g_W1h[(K1 + 1) * DD * DD];
__device__ __align__(16) __half g_W2h[(K2 + 1) * DD * DD];
__device__ __align__(16) __half g_Wch[DD * DD];

// ---------------- build kernels ------------------------------------------------
__global__ void k_zero() {
    int i = blockIdx.x * blockDim.x + threadIdx.x;
    if (i < NN) { g_deg[i] = 0; g_cursor[i] = 0; }
}

__global__ void k_deg(const int* __restrict__ ei) {
    int e = blockIdx.x * blockDim.x + threadIdx.x;
    if (e < EE) atomicAdd(&g_deg[ei[EE + e]], 1);
}

// block-scan of deg -> g_off[i+1] (local), block sums -> g_part; also dinv
__global__ void k_scan1() {
    __shared__ int sd[1024];
    int b = blockIdx.x, t = threadIdx.x;
    int i = b * 1024 + t;
    int v = (i < NN) ? g_deg[i] : 0;
    if (i < NN) {
        float d = (float)v;
        g_dinv[i] = (d > 0.0f) ? rsqrtf(d) : 0.0f;
    }
    sd[t] = v;
    __syncthreads();
    for (int off = 1; off < 1024; off <<= 1) {
        int x = sd[t];
        if (t >= off) x += sd[t - off];
        __syncthreads();
        sd[t] = x;
        __syncthreads();
    }
    if (i < NN) g_off[i + 1] = sd[t];
    if (t == 1023) g_part[b] = sd[1023];
}

// each block recomputes the 98-partial prefix locally, adds to its g_off range
__global__ void k_scan3() {
    __shared__ int sp[128];
    int b = blockIdx.x, t = threadIdx.x;
    if (t < 128) sp[t] = (t < NB_SCAN) ? g_part[t] : 0;
    __syncthreads();
    for (int off = 1; off < 128; off <<= 1) {
        int x = 0;
        if (t < 128) { x = sp[t]; if (t >= off) x += sp[t - off]; }
        __syncthreads();
        if (t < 128) sp[t] = x;
        __syncthreads();
    }
    int add = (b > 0) ? sp[b - 1] : 0;
    int i = b * 1024 + t;
    if (i < NN) g_off[i + 1] += add;
    if (b == 0 && t == 0) g_off[0] = 0;
}

// fused: CSC fill (edges) + x -> fp16 slice0 copy. grid = NN*32/256 = 12500
__global__ void k_fillcopy(const int* __restrict__ ei, const float* __restrict__ x) {
    int i = blockIdx.x * blockDim.x + threadIdx.x;
    if (i < NN * 32) {
        float2 v = ((const float2*)x)[i];
        ((__half2*)g_S1)[i] = __floats2half2_rn(v.x, v.y);
    }
    if (i < EE) {
        int r = ei[i];
        int c = ei[EE + i];
        int p = g_off[c] + atomicAdd(&g_cursor[c], 1);
        g_csc[p] = make_int2(r, __float_as_int(g_dinv[r] * g_dinv[c]));
    }
}

// weights fp32 -> fp16 (one tiny launch)
__global__ void k_cvtw(const float* __restrict__ w1, const float* __restrict__ w2,
                       const float* __restrict__ wc) {
    int i = blockIdx.x * blockDim.x + threadIdx.x;
    if (i < (K1 + 1) * DD * DD) g_W1h[i] = __float2half_rn(w1[i]);
    if (i < (K2 + 1) * DD * DD) g_W2h[i] = __float2half_rn(w2[i]);
    if (i < DD * DD)            g_Wch[i] = __float2half_rn(wc[i]);
}

// ---------------- SpMM: warp per dst node, 4 edges/iteration -------------------
// lanes: eg = lane>>3 (edge group 0..3), c = lane&7 (16B chunk of 128B row).
// Per iteration: 1x LDG.64 csc (4 contiguous records) + 1x LDG.128 features.
__global__ void __launch_bounds__(256) k_spmm(int layer, int si, int so) {
    int warp = (blockIdx.x * blockDim.x + threadIdx.x) >> 5;
    int lane = threadIdx.x & 31;
    if (warp >= NN) return;
    const __half* base = layer ? g_S2 : g_S1;
    const __half* __restrict__ hin = base + (size_t)si * NN * DD;
    __half* __restrict__ hout = (layer ? g_S2 : g_S1) + (size_t)so * NN * DD;
    int s = g_off[warp], eend = g_off[warp + 1];
    int eg = lane >> 3, c = lane & 7;

    float acc[8];
#pragma unroll
    for (int j = 0; j < 8; j++) acc[j] = 0.f;

#pragma unroll 2
    for (int p = s + eg; p < eend; p += 4) {
        int2 sw = __ldg(&g_csc[p]);
        float wt = __int_as_float(sw.y);
        uint4 v = __ldg((const uint4*)(hin + (size_t)sw.x * DD) + c);
        float2 f0 = __half22float2(*(__half2*)&v.x);
        float2 f1 = __half22float2(*(__half2*)&v.y);
        float2 f2 = __half22float2(*(__half2*)&v.z);
        float2 f3 = __half22float2(*(__half2*)&v.w);
        acc[0] += wt * f0.x; acc[1] += wt * f0.y;
        acc[2] += wt * f1.x; acc[3] += wt * f1.y;
        acc[4] += wt * f2.x; acc[5] += wt * f2.y;
        acc[6] += wt * f3.x; acc[7] += wt * f3.y;
    }

    // reduce across the 4 edge groups (lanes differing in bits 3,4)
#pragma unroll
    for (int j = 0; j < 8; j++) {
        acc[j] += __shfl_xor_sync(0xffffffffu, acc[j], 8);
        acc[j] += __shfl_xor_sync(0xffffffffu, acc[j], 16);
    }

    if (eg == 0) {
        __half2 h0 = __floats2half2_rn(acc[0], acc[1]);
        __half2 h1 = __floats2half2_rn(acc[2], acc[3]);
        __half2 h2 = __floats2half2_rn(acc[4], acc[5]);
        __half2 h3 = __floats2half2_rn(acc[6], acc[7]);
        uint4 o;
        o.x = *(uint32_t*)&h0; o.y = *(uint32_t*)&h1;
        o.z = *(uint32_t*)&h2; o.w = *(uint32_t*)&h3;
        *((uint4*)(hout + (size_t)warp * DD) + c) = o;
    }
}

// ---------------- tensor-core multi-slice GEMM ---------------------------------
// C[r][c] = (tanh?)( sum_s A_s[r][:] . W_s[:][c] + bias[c] ), fp16 in, fp32 acc.
__global__ void __launch_bounds__(256, 2) k_mma(
    int whichA, int nsl, int whichW,
    const float* __restrict__ bias,
    int whichOut, float* __restrict__ dext, int dotanh)
{
    __shared__ __half As[256 * 72];   // A tile, 72-half padded rows
    __shared__ __half Ws[64 * 72];    // W^T tile: [n][k], 72-half padded rows

    const __half* A = (whichA == 0) ? g_S1 : (whichA == 1) ? g_S2 : g_Sf;
    const __half* W = (whichW == 0) ? g_W1h : (whichW == 1) ? g_W2h : g_Wch;
    __half* OutH = (whichOut == 0) ? g_S2 : g_Sf;

    int t = threadIdx.x, w = t >> 5, l = t & 31;
    int rowBase = blockIdx.x * 256;

    float acc[2][8][4];
#pragma unroll
    for (int rf = 0; rf < 2; rf++)
#pragma unroll
        for (int j = 0; j < 8; j++)
#pragma unroll
            for (int q = 0; q < 4; q++) acc[rf][j][q] = 0.f;

    for (int s = 0; s < nsl; s++) {
        const __half* Ag = A + (size_t)s * NN * DD;
#pragma unroll
        for (int it = 0; it < 8; it++) {
            int idx = it * 256 + t;              // 0..2047
            int row = idx >> 3, c16 = idx & 7;
            int gr = rowBase + row;
            uint4 v = make_uint4(0, 0, 0, 0);
            if (gr < NN) v = *(const uint4*)(Ag + (size_t)gr * DD + c16 * 8);
            *(uint4*)(&As[row * 72 + c16 * 8]) = v;
        }
        const __half* Wg = W + s * DD * DD;
#pragma unroll
        for (int it = 0; it < 16; it++) {
            int idx = it * 256 + t;              // 0..4095
            int k = idx >> 6, n = idx & 63;
            Ws[n * 72 + k] = Wg[idx];
        }
        __syncthreads();

#pragma unroll
        for (int ks = 0; ks < 4; ks++) {
            uint32_t a[2][4];
#pragma unroll
            for (int rf = 0; rf < 2; rf++) {
                int row = w * 32 + rf * 16 + (l & 15);
                uint32_t addr = (uint32_t)__cvta_generic_to_shared(
                    &As[row * 72 + ks * 16 + (l >> 4) * 8]);
                asm volatile("ldmatrix.sync.aligned.m8n8.x4.shared.b16 {%0,%1,%2,%3},[%4];"
                             : "=r"(a[rf][0]), "=r"(a[rf][1]), "=r"(a[rf][2]), "=r"(a[rf][3])
                             : "r"(addr));
            }
#pragma unroll
            for (int j = 0; j < 8; j++) {
                int n = j * 8 + (l >> 2);
                int kk = ks * 16 + (l & 3) * 2;
                uint32_t b0 = *(const uint32_t*)(&Ws[n * 72 + kk]);
                uint32_t b1 = *(const uint32_t*)(&Ws[n * 72 + kk + 8]);
#pragma unroll
                for (int rf = 0; rf < 2; rf++) {
                    asm volatile(
                        "mma.sync.aligned.m16n8k16.row.col.f32.f16.f16.f32 "
                        "{%0,%1,%2,%3},{%4,%5,%6,%7},{%8,%9},{%0,%1,%2,%3};"
                        : "+f"(acc[rf][j][0]), "+f"(acc[rf][j][1]),
                          "+f"(acc[rf][j][2]), "+f"(acc[rf][j][3])
                        : "r"(a[rf][0]), "r"(a[rf][1]), "r"(a[rf][2]), "r"(a[rf][3]),
                          "r"(b0), "r"(b1));
                }
            }
        }
        __syncthreads();
    }

#pragma unroll
    for (int rf = 0; rf < 2; rf++) {
#pragma unroll
        for (int j = 0; j < 8; j++) {
            int r0 = rowBase + w * 32 + rf * 16 + (l >> 2);
            int c = j * 8 + (l & 3) * 2;
            float v0 = acc[rf][j][0] + bias[c];
            float v1 = acc[rf][j][1] + bias[c + 1];
            float v2 = acc[rf][j][2] + bias[c];
            float v3 = acc[rf][j][3] + bias[c + 1];
            if (dotanh) {
                v0 = tanhf(v0); v1 = tanhf(v1);
                v2 = tanhf(v2); v3 = tanhf(v3);
            }
            if (whichOut == 2) {
                if (r0 < NN)     *(float2*)&dext[(size_t)r0 * DD + c]       = make_float2(v0, v1);
                if (r0 + 8 < NN) *(float2*)&dext[(size_t)(r0 + 8) * DD + c] = make_float2(v2, v3);
            } else {
                if (r0 < NN)     *(__half2*)&OutH[(size_t)r0 * DD + c]       = __floats2half2_rn(v0, v1);
                if (r0 + 8 < NN) *(__half2*)&OutH[(size_t)(r0 + 8) * DD + c] = __floats2half2_rn(v2, v3);
            }
        }
    }
}

// ---------------- launch -------------------------------------------------------
extern "C" void kernel_launch(void* const* d_in, const int* in_sizes, int n_in,
                              void* d_out, int out_size) {
    const float* x  = (const float*)d_in[0];
    const int*   ei = (const int*)d_in[1];     // int32 edge_index [2, E]
    const float* w1 = (const float*)d_in[2];
    const float* b1 = (const float*)d_in[3];
    const float* w2 = (const float*)d_in[4];
    const float* b2 = (const float*)d_in[5];
    const float* wc = (const float*)d_in[6];
    const float* bc = (const float*)d_in[7];
    float* out = (float*)d_out;

    // ---- build ----
    k_zero<<<(NN + 255) / 256, 256>>>();
    k_deg<<<(EE + 255) / 256, 256>>>(ei);
    k_scan1<<<NB_SCAN, 1024>>>();
    k_scan3<<<NB_SCAN, 1024>>>();
    k_fillcopy<<<(NN * 32 + 255) / 256, 256>>>(ei, x);

    int spmm_blocks = (NN * 32 + 255) / 256;
    for (int k = 1; k <= K1; k++)
        k_spmm<<<spmm_blocks, 256>>>(0, k - 1, k);

    k_cvtw<<<((K1 + 1) * DD * DD + 255) / 256, 256>>>(w1, w2, wc);

    int gemm_blocks = (NN + 255) / 256;
    // layer1: tanh(sum H1_k W1_k + b1) -> g_S2 slice 0 (fp16)
    k_mma<<<gemm_blocks, 256>>>(0, K1 + 1, 0, b1, 0, nullptr, 1);

    for (int k = 1; k <= K2; k++)
        k_spmm<<<spmm_blocks, 256>>>(1, k - 1, k);
    // layer2: tanh(sum H2_k W2_k + b2) -> g_Sf (fp16)
    k_mma<<<gemm_blocks, 256>>>(1, K2 + 1, 1, b2, 1, nullptr, 1);

    // final linear -> d_out (fp32)
    k_mma<<<gemm_blocks, 256>>>(2, 1, 2, bc, 2, out, 0);
}